// round 8
// baseline (speedup 1.0000x reference)
#include <cuda_runtime.h>
#include <cstdint>

#define EMBED  512
#define CONVC  512
#define HID    1024
#define LABELS 128
#define M_TOTAL (32 * 1024)

// Scratch (allocation-free rule -> __device__ globals). tf32-bit payloads in float containers.
__device__ float g_h[(size_t)M_TOTAL * CONVC];   // 64 MB (tf32 bits)
__device__ float g_z[(size_t)M_TOTAL * HID];     // 128 MB (tf32 bits)
__device__ float g_w0[(size_t)CONVC * EMBED];    // conv_w tf32 [N,K]
__device__ float g_w1t[(size_t)HID * CONVC];     // w1^T tf32 [1024,512]
__device__ float g_w2t[(size_t)LABELS * HID];    // w2^T tf32 [128,1024]

__device__ __forceinline__ uint32_t smem_u32(const void* p) {
    uint32_t a;
    asm("{ .reg .u64 t; cvta.to.shared.u64 t, %1; cvt.u32.u64 %0, t; }" : "=r"(a) : "l"(p));
    return a;
}
__device__ __forceinline__ uint32_t f2tf32(float x) {
    uint32_t y; asm("cvt.rna.tf32.f32 %0, %1;" : "=r"(y) : "f"(x)); return y;
}
__device__ __forceinline__ float tf32f(float x) { return __uint_as_float(f2tf32(x)); }

#define CP_ASYNC16(dst, src) \
    asm volatile("cp.async.cg.shared.global [%0], [%1], 16;" :: "r"(dst), "l"(src))
#define CP_COMMIT() asm volatile("cp.async.commit_group;" ::: "memory")
#define CP_WAIT2()  asm volatile("cp.async.wait_group 2;" ::: "memory")

#define LDSM_X4(r0, r1, r2, r3, addr) \
    asm volatile("ldmatrix.sync.aligned.m8n8.x4.shared.b16 {%0,%1,%2,%3}, [%4];" \
        : "=r"(r0), "=r"(r1), "=r"(r2), "=r"(r3) : "r"(addr))
#define LDSM_X2(r0, r1, addr) \
    asm volatile("ldmatrix.sync.aligned.m8n8.x2.shared.b16 {%0,%1}, [%2];" \
        : "=r"(r0), "=r"(r1) : "r"(addr))

__device__ __forceinline__ void mma_tf32(float* c, const uint32_t* a, const uint32_t* b) {
    asm volatile(
        "mma.sync.aligned.m16n8k8.row.col.f32.tf32.tf32.f32 "
        "{%0,%1,%2,%3}, {%4,%5,%6,%7}, {%8,%9}, {%0,%1,%2,%3};\n"
        : "+f"(c[0]), "+f"(c[1]), "+f"(c[2]), "+f"(c[3])
        : "r"(a[0]), "r"(a[1]), "r"(a[2]), "r"(a[3]), "r"(b[0]), "r"(b[1]));
}

// ---------------- pipelined tf32 GEMM ----------------
// C[M, N_TOTAL] = act(A[M,K] @ Wt[N,K]^T + bias). Wt already tf32 bits, k-major.
// GATHER: A rows gathered from emb_table via token ids, converted to tf32 in-kernel.
// BM=256, BN=128, BK=32. 8 warps (4x2), warp tile 64x64. 3-stage ring.
template <int N_TOTAL, int K, bool GATHER, bool RELU, bool CVT_OUT>
__global__ __launch_bounds__(256, 1)
void gemm_pipe(const float* __restrict__ A, const int* __restrict__ tok,
               const float* __restrict__ Wt, const float* __restrict__ bias,
               float* __restrict__ C) {
    constexpr int BM = 256, BN = 128, BK = 32;
    constexpr int KCH = K / BK;
    constexpr int PITCH = 36;                      // floats per smem row
    constexpr int ROWB = PITCH * 4;                // 144 bytes
    constexpr int A_BYTES = BM * ROWB;             // 36864
    constexpr int B_BYTES = BN * ROWB;             // 18432
    constexpr int STAGE = A_BYTES + B_BYTES;       // 55296

    extern __shared__ char smem[];
    const uint32_t sb = smem_u32(smem);
    int* stok = (int*)(smem + 3 * STAGE);

    const int tid  = threadIdx.x;
    const int warp = tid >> 5, lane = tid & 31;
    const int grp  = lane >> 2, tig = lane & 3;
    const int wm   = warp >> 1, wn = warp & 1;

    const int bm = blockIdx.y * BM;
    const int bn = blockIdx.x * BN;

    // ldmatrix per-lane byte offsets (within stage A / stage B regions)
    const int j  = lane >> 3;         // 0..3
    const int r8 = lane & 7;
    uint32_t offA[4], offB[8];
#pragma unroll
    for (int mi = 0; mi < 4; mi++)
        offA[mi] = (uint32_t)((wm * 64 + mi * 16 + (j & 1) * 8 + r8) * ROWB + (j >> 1) * 16);
#pragma unroll
    for (int ni = 0; ni < 8; ni++)
        offB[ni] = (uint32_t)((wn * 64 + ni * 8 + r8) * ROWB + (j & 1) * 16);

    // ---- loaders ----
    auto issueA = [&](int s, int kt) {             // cp.async path (pre-tf32 A)
        const int k0 = kt * BK;
        const uint32_t ab = sb + s * STAGE;
#pragma unroll
        for (int i = 0; i < 8; i++) {
            int idx = tid + i * 256;
            int rr = idx >> 3, c4 = idx & 7;
            CP_ASYNC16(ab + (uint32_t)(rr * ROWB + c4 * 16),
                       A + (size_t)(bm + rr) * K + k0 + c4 * 4);
        }
    };
    auto issueB = [&](int s, int kt) {
        const int k0 = kt * BK;
        const uint32_t bb = sb + s * STAGE + A_BYTES;
#pragma unroll
        for (int i = 0; i < 4; i++) {
            int idx = tid + i * 256;
            int rr = idx >> 3, c4 = idx & 7;
            CP_ASYNC16(bb + (uint32_t)(rr * ROWB + c4 * 16),
                       Wt + (size_t)(bn + rr) * K + k0 + c4 * 4);
        }
    };

    float4 areg[8];                                // gather path register staging
    auto ldA = [&](int kt) {
        const int k0 = kt * BK;
#pragma unroll
        for (int i = 0; i < 8; i++) {
            int idx = tid + i * 256;
            int rr = idx >> 3, c4 = idx & 7;
            areg[i] = *(const float4*)(A + (size_t)stok[rr] * K + k0 + c4 * 4);
        }
    };
    auto stA = [&](int s) {
        const uint32_t ab = sb + s * STAGE;
#pragma unroll
        for (int i = 0; i < 8; i++) {
            int idx = tid + i * 256;
            int rr = idx >> 3, c4 = idx & 7;
            uint32_t dst = ab + (uint32_t)(rr * ROWB + c4 * 16);
            asm volatile("st.shared.v4.b32 [%0], {%1, %2, %3, %4};" ::
                "r"(dst), "r"(f2tf32(areg[i].x)), "r"(f2tf32(areg[i].y)),
                "r"(f2tf32(areg[i].z)), "r"(f2tf32(areg[i].w)));
        }
    };

    float acc[4][8][4];
#pragma unroll
    for (int mi = 0; mi < 4; mi++)
#pragma unroll
        for (int ni = 0; ni < 8; ni++)
#pragma unroll
            for (int q = 0; q < 4; q++) acc[mi][ni][q] = 0.0f;

    // ---- prologue ----
    if (GATHER) {
        stok[tid] = tok[bm + tid];
        __syncthreads();
        ldA(0); stA(0); ldA(1);
        issueB(0, 0); CP_COMMIT();
        issueB(1, 1); CP_COMMIT();
    } else {
        issueA(0, 0); issueB(0, 0); CP_COMMIT();
        issueA(1, 1); issueB(1, 1); CP_COMMIT();
    }

    // ---- main loop ----
    for (int kt = 0; kt < KCH; kt++) {
        const int s = kt % 3;
        if (kt + 2 < KCH) {
            if (!GATHER) issueA((kt + 2) % 3, kt + 2);
            issueB((kt + 2) % 3, kt + 2);
        }
        CP_COMMIT();
        CP_WAIT2();
        if (GATHER) {
            if (kt + 1 < KCH) stA((kt + 1) % 3);
            if (kt + 2 < KCH) ldA(kt + 2);
        }
        __syncthreads();

        const uint32_t sA = sb + s * STAGE;
        const uint32_t sB = sA + A_BYTES;
#pragma unroll
        for (int ks = 0; ks < 4; ks++) {
            const int kb = ks * 32;                // 8 floats = 32 bytes per k-step
            uint32_t a[4][4], b[8][2];
#pragma unroll
            for (int mi = 0; mi < 4; mi++)
                LDSM_X4(a[mi][0], a[mi][1], a[mi][2], a[mi][3], sA + offA[mi] + kb);
#pragma unroll
            for (int ni = 0; ni < 8; ni++)
                LDSM_X2(b[ni][0], b[ni][1], sB + offB[ni] + kb);
#pragma unroll
            for (int mi = 0; mi < 4; mi++)
#pragma unroll
                for (int ni = 0; ni < 8; ni++)
                    mma_tf32(acc[mi][ni], a[mi], b[ni]);
        }
        __syncthreads();
    }

    // ---- epilogue: bias (+relu) (+tf32 re-quant for chained GEMMs) ----
#pragma unroll
    for (int ni = 0; ni < 8; ni++) {
        const int n = bn + wn * 64 + ni * 8 + tig * 2;
        const float bv0 = __ldg(&bias[n]);
        const float bv1 = __ldg(&bias[n + 1]);
#pragma unroll
        for (int mi = 0; mi < 4; mi++) {
            const int m0 = bm + wm * 64 + mi * 16 + grp;
            float v0 = acc[mi][ni][0] + bv0;
            float v1 = acc[mi][ni][1] + bv1;
            float v2 = acc[mi][ni][2] + bv0;
            float v3 = acc[mi][ni][3] + bv1;
            if (RELU) {
                v0 = fmaxf(v0, 0.0f); v1 = fmaxf(v1, 0.0f);
                v2 = fmaxf(v2, 0.0f); v3 = fmaxf(v3, 0.0f);
            }
            if (CVT_OUT) {
                v0 = tf32f(v0); v1 = tf32f(v1); v2 = tf32f(v2); v3 = tf32f(v3);
            }
            *(float2*)(C + (size_t)m0 * N_TOTAL + n)       = make_float2(v0, v1);
            *(float2*)(C + (size_t)(m0 + 8) * N_TOTAL + n) = make_float2(v2, v3);
        }
    }
}

// ---------------- prep kernels ----------------
__global__ __launch_bounds__(256)
void cvt_kernel(const float* __restrict__ in, float* __restrict__ out) {
    const int i4 = blockIdx.x * 256 + threadIdx.x;
    const float4 v = *(const float4*)(in + (size_t)i4 * 4);
    *(float4*)(out + (size_t)i4 * 4) = make_float4(tf32f(v.x), tf32f(v.y), tf32f(v.z), tf32f(v.w));
}

__global__ void transpose_cvt_kernel(const float* __restrict__ in, float* __restrict__ out,
                                     int R, int Ccols) {
    __shared__ float t[32][33];
    int bx = blockIdx.x * 32, by = blockIdx.y * 32;
    int x = bx + threadIdx.x;
#pragma unroll
    for (int jj = 0; jj < 32; jj += 8) {
        int y = by + threadIdx.y + jj;
        t[threadIdx.y + jj][threadIdx.x] = in[(size_t)y * Ccols + x];
    }
    __syncthreads();
    x = by + threadIdx.x;
#pragma unroll
    for (int jj = 0; jj < 32; jj += 8) {
        int y = bx + threadIdx.y + jj;
        out[(size_t)y * R + x] = tf32f(t[threadIdx.x][threadIdx.y + jj]);
    }
}

extern "C" void kernel_launch(void* const* d_in, const int* in_sizes, int n_in,
                              void* d_out, int out_size) {
    const int*   tok    = (const int*)d_in[0];
    const float* emb    = (const float*)d_in[1];
    const float* conv_w = (const float*)d_in[2];   // [CONVC, EMBED] = [N,K]
    const float* conv_b = (const float*)d_in[3];
    const float* w1     = (const float*)d_in[4];   // [CONVC, HID]
    const float* b1     = (const float*)d_in[5];
    const float* w2     = (const float*)d_in[6];   // [HID, LABELS]
    const float* b2     = (const float*)d_in[7];
    float* out = (float*)d_out;

    float *h_buf, *z_buf, *w0, *w1t, *w2t;
    cudaGetSymbolAddress((void**)&h_buf, g_h);
    cudaGetSymbolAddress((void**)&z_buf, g_z);
    cudaGetSymbolAddress((void**)&w0,  g_w0);
    cudaGetSymbolAddress((void**)&w1t, g_w1t);
    cudaGetSymbolAddress((void**)&w2t, g_w2t);

    constexpr int SMEM = 3 * (256 * 36 * 4 + 128 * 36 * 4) + 1024;   // 166912
    cudaFuncSetAttribute(gemm_pipe<CONVC, EMBED, true,  true,  true>,
                         cudaFuncAttributeMaxDynamicSharedMemorySize, SMEM);
    cudaFuncSetAttribute(gemm_pipe<HID, CONVC, false, true,  true>,
                         cudaFuncAttributeMaxDynamicSharedMemorySize, SMEM);
    cudaFuncSetAttribute(gemm_pipe<LABELS, HID, false, false, false>,
                         cudaFuncAttributeMaxDynamicSharedMemorySize, SMEM);

    // Prep: cvt conv_w, transpose+cvt w1/w2 (bandwidth-trivial)
    cvt_kernel<<<(CONVC * EMBED / 4) / 256, 256>>>(conv_w, w0);
    transpose_cvt_kernel<<<dim3(HID / 32, CONVC / 32), dim3(32, 8)>>>(w1, w1t, CONVC, HID);
    transpose_cvt_kernel<<<dim3(LABELS / 32, HID / 32), dim3(32, 8)>>>(w2, w2t, HID, LABELS);

    // GEMM1: h = tf32(relu(emb[tok] @ conv_w^T + conv_b))   [32768, 512]  (gather fused)
    gemm_pipe<CONVC, EMBED, true, true, true>
        <<<dim3(CONVC / 128, M_TOTAL / 256), 256, SMEM>>>(emb, tok, w0, conv_b, h_buf);
    // GEMM2: z = tf32(relu(h @ w1 + b1))                    [32768, 1024]
    gemm_pipe<HID, CONVC, false, true, true>
        <<<dim3(HID / 128, M_TOTAL / 256), 256, SMEM>>>(h_buf, nullptr, w1t, b1, z_buf);
    // GEMM3: out = z @ w2 + b2                              [32768, 128]
    gemm_pipe<LABELS, HID, false, false, false>
        <<<dim3(LABELS / 128, M_TOTAL / 256), 256, SMEM>>>(z_buf, nullptr, w2t, b2, out);
}

// round 9
// speedup vs baseline: 2.5099x; 2.5099x over previous
#include <cuda_runtime.h>
#include <cuda_fp16.h>
#include <cstdint>

#define EMBED  512
#define CONVC  512
#define HID    1024
#define LABELS 128
#define M_TOTAL (32 * 1024)

// Scratch (allocation-free rule -> __device__ globals). fp16 payloads.
__device__ __half g_x[(size_t)M_TOTAL * EMBED];   // gathered fp16 embeddings, 32 MB
__device__ __half g_h[(size_t)M_TOTAL * CONVC];   // 32 MB
__device__ __half g_z[(size_t)M_TOTAL * HID];     // 64 MB
__device__ __half g_w0[(size_t)CONVC * EMBED];    // conv_w fp16 [N,K]
__device__ __half g_w1t[(size_t)HID * CONVC];     // w1^T fp16 [1024,512]
__device__ __half g_w2t[(size_t)LABELS * HID];    // w2^T fp16 [128,1024]

__device__ __forceinline__ uint32_t smem_u32(const void* p) {
    uint32_t a;
    asm("{ .reg .u64 t; cvta.to.shared.u64 t, %1; cvt.u32.u64 %0, t; }" : "=r"(a) : "l"(p));
    return a;
}

#define CP_ASYNC16(dst, src) \
    asm volatile("cp.async.cg.shared.global [%0], [%1], 16;" :: "r"(dst), "l"(src))
#define CP_COMMIT() asm volatile("cp.async.commit_group;" ::: "memory")
#define CP_WAIT2()  asm volatile("cp.async.wait_group 2;" ::: "memory")

__device__ __forceinline__ void mma_f16(float* c, const uint32_t* a, const uint32_t* b) {
    asm volatile(
        "mma.sync.aligned.m16n8k16.row.col.f32.f16.f16.f32 "
        "{%0,%1,%2,%3}, {%4,%5,%6,%7}, {%8,%9}, {%0,%1,%2,%3};\n"
        : "+f"(c[0]), "+f"(c[1]), "+f"(c[2]), "+f"(c[3])
        : "r"(a[0]), "r"(a[1]), "r"(a[2]), "r"(a[3]), "r"(b[0]), "r"(b[1]));
}

// ---------------- pipelined fp16 GEMM ----------------
// C[M, N_TOTAL] = act(A[M,K] @ Wt[N,K]^T + bias). A, Wt fp16; accumulate fp32.
// BM=256, BN=128, BK=64 (halves). 8 warps (4x2), warp tile 64x64. 3-stage cp.async ring.
template <int N_TOTAL, int K, bool RELU, bool HALF_OUT>
__global__ __launch_bounds__(256, 1)
void gemm_pipe_h(const __half* __restrict__ A, const __half* __restrict__ Wt,
                 const float* __restrict__ bias, void* __restrict__ Cv) {
    constexpr int BM = 256, BN = 128, BK = 64;     // BK in halves = 128 B
    constexpr int KCH = K / BK;
    constexpr int P32 = 36;                        // u32 per smem row (72 halves, pad 8)
    constexpr int ROWB = P32 * 4;                  // 144 bytes
    constexpr int A_BYTES = BM * ROWB;             // 36864
    constexpr int B_BYTES = BN * ROWB;             // 18432
    constexpr int STAGE = A_BYTES + B_BYTES;       // 55296

    extern __shared__ char smem[];
    const uint32_t sb = smem_u32(smem);

    const int tid  = threadIdx.x;
    const int warp = tid >> 5, lane = tid & 31;
    const int grp  = lane >> 2, tig = lane & 3;
    const int wm   = warp >> 1, wn = warp & 1;

    const int bm = blockIdx.y * BM;
    const int bn = blockIdx.x * BN;

    // stage fill: A 256 rows x 8 chunks(16B), B 128 rows x 8 chunks
    auto issue = [&](int s, int kt) {
        const int k0 = kt * BK;
        const uint32_t ab = sb + s * STAGE;
        const uint32_t bb = ab + A_BYTES;
#pragma unroll
        for (int i = 0; i < 8; i++) {
            int idx = tid + i * 256;
            int r = idx >> 3, c4 = idx & 7;
            CP_ASYNC16(ab + (uint32_t)(r * ROWB + c4 * 16),
                       A + (size_t)(bm + r) * K + k0 + c4 * 8);
        }
#pragma unroll
        for (int i = 0; i < 4; i++) {
            int idx = tid + i * 256;
            int r = idx >> 3, c4 = idx & 7;
            CP_ASYNC16(bb + (uint32_t)(r * ROWB + c4 * 16),
                       Wt + (size_t)(bn + r) * K + k0 + c4 * 8);
        }
    };

    float acc[4][8][4];
#pragma unroll
    for (int mi = 0; mi < 4; mi++)
#pragma unroll
        for (int ni = 0; ni < 8; ni++)
#pragma unroll
            for (int q = 0; q < 4; q++) acc[mi][ni][q] = 0.0f;

    issue(0, 0); CP_COMMIT();
    issue(1, 1); CP_COMMIT();

    for (int kt = 0; kt < KCH; kt++) {
        const int s = kt % 3;
        if (kt + 2 < KCH) issue((kt + 2) % 3, kt + 2);
        CP_COMMIT();
        CP_WAIT2();
        __syncthreads();

        const uint32_t* As = (const uint32_t*)(smem + s * STAGE);
        const uint32_t* Bs = (const uint32_t*)(smem + s * STAGE + A_BYTES);
#pragma unroll
        for (int ks = 0; ks < 4; ks++) {           // 4 x k16 steps (8 u32 each)
            const int kk = ks * 8;
            uint32_t a[4][4], b[8][2];
#pragma unroll
            for (int mi = 0; mi < 4; mi++) {
                int r = wm * 64 + mi * 16 + grp;
                a[mi][0] = As[r * P32 + kk + tig];          // rows grp / grp+8, k pair 2tig
                a[mi][1] = As[(r + 8) * P32 + kk + tig];
                a[mi][2] = As[r * P32 + kk + tig + 4];      // k pair 2tig+8
                a[mi][3] = As[(r + 8) * P32 + kk + tig + 4];
            }
#pragma unroll
            for (int ni = 0; ni < 8; ni++) {
                int n = wn * 64 + ni * 8 + grp;
                b[ni][0] = Bs[n * P32 + kk + tig];
                b[ni][1] = Bs[n * P32 + kk + tig + 4];
            }
#pragma unroll
            for (int mi = 0; mi < 4; mi++)
#pragma unroll
                for (int ni = 0; ni < 8; ni++)
                    mma_f16(acc[mi][ni], a[mi], b[ni]);
        }
        __syncthreads();
    }

    // Epilogue: bias (+relu); store fp16 (chained) or fp32 (final)
#pragma unroll
    for (int ni = 0; ni < 8; ni++) {
        const int n = bn + wn * 64 + ni * 8 + tig * 2;
        const float bv0 = __ldg(&bias[n]);
        const float bv1 = __ldg(&bias[n + 1]);
#pragma unroll
        for (int mi = 0; mi < 4; mi++) {
            const int m0 = bm + wm * 64 + mi * 16 + grp;
            float v0 = acc[mi][ni][0] + bv0;
            float v1 = acc[mi][ni][1] + bv1;
            float v2 = acc[mi][ni][2] + bv0;
            float v3 = acc[mi][ni][3] + bv1;
            if (RELU) {
                v0 = fmaxf(v0, 0.0f); v1 = fmaxf(v1, 0.0f);
                v2 = fmaxf(v2, 0.0f); v3 = fmaxf(v3, 0.0f);
            }
            if (HALF_OUT) {
                __half* C = (__half*)Cv;
                *(__half2*)(C + (size_t)m0 * N_TOTAL + n)       = __floats2half2_rn(v0, v1);
                *(__half2*)(C + (size_t)(m0 + 8) * N_TOTAL + n) = __floats2half2_rn(v2, v3);
            } else {
                float* C = (float*)Cv;
                *(float2*)(C + (size_t)m0 * N_TOTAL + n)       = make_float2(v0, v1);
                *(float2*)(C + (size_t)(m0 + 8) * N_TOTAL + n) = make_float2(v2, v3);
            }
        }
    }
}

// ---------------- prep kernels ----------------
// Gather embedding rows -> fp16: x[m,:] = half(emb[tok[m],:])
__global__ __launch_bounds__(256)
void gather_h_kernel(const int* __restrict__ tok, const float* __restrict__ emb,
                     __half* __restrict__ out) {
    const int i4 = blockIdx.x * 256 + threadIdx.x;          // one float4 each
    const int row = i4 >> 7;                                 // EMBED/4 = 128
    const int c   = (i4 & 127) << 2;
    const float4 v = *(const float4*)(emb + (size_t)tok[row] * EMBED + c);
    __half2 h0 = __floats2half2_rn(v.x, v.y);
    __half2 h1 = __floats2half2_rn(v.z, v.w);
    *(uint2*)(out + (size_t)row * EMBED + c) =
        make_uint2(*(uint32_t*)&h0, *(uint32_t*)&h1);
}

// Elementwise fp16 convert (conv_w already [N,K])
__global__ __launch_bounds__(256)
void cvt_h_kernel(const float* __restrict__ in, __half* __restrict__ out) {
    const int i4 = blockIdx.x * 256 + threadIdx.x;
    const float4 v = *(const float4*)(in + (size_t)i4 * 4);
    __half2 h0 = __floats2half2_rn(v.x, v.y);
    __half2 h1 = __floats2half2_rn(v.z, v.w);
    *(uint2*)(out + (size_t)i4 * 4) = make_uint2(*(uint32_t*)&h0, *(uint32_t*)&h1);
}

// Transpose [R,C] -> [C,R] with fp16 convert
__global__ void transpose_h_kernel(const float* __restrict__ in, __half* __restrict__ out,
                                   int R, int Ccols) {
    __shared__ float t[32][33];
    int bx = blockIdx.x * 32, by = blockIdx.y * 32;
    int x = bx + threadIdx.x;
#pragma unroll
    for (int j = 0; j < 32; j += 8) {
        int y = by + threadIdx.y + j;
        t[threadIdx.y + j][threadIdx.x] = in[(size_t)y * Ccols + x];
    }
    __syncthreads();
    x = by + threadIdx.x;
#pragma unroll
    for (int j = 0; j < 32; j += 8) {
        int y = bx + threadIdx.y + j;
        out[(size_t)y * R + x] = __float2half_rn(t[threadIdx.x][threadIdx.y + j]);
    }
}

extern "C" void kernel_launch(void* const* d_in, const int* in_sizes, int n_in,
                              void* d_out, int out_size) {
    const int*   tok    = (const int*)d_in[0];
    const float* emb    = (const float*)d_in[1];
    const float* conv_w = (const float*)d_in[2];   // [CONVC, EMBED] = [N,K]
    const float* conv_b = (const float*)d_in[3];
    const float* w1     = (const float*)d_in[4];   // [CONVC, HID]
    const float* b1     = (const float*)d_in[5];
    const float* w2     = (const float*)d_in[6];   // [HID, LABELS]
    const float* b2     = (const float*)d_in[7];
    float* out = (float*)d_out;

    __half *x_buf, *h_buf, *z_buf, *w0, *w1t, *w2t;
    cudaGetSymbolAddress((void**)&x_buf, g_x);
    cudaGetSymbolAddress((void**)&h_buf, g_h);
    cudaGetSymbolAddress((void**)&z_buf, g_z);
    cudaGetSymbolAddress((void**)&w0,  g_w0);
    cudaGetSymbolAddress((void**)&w1t, g_w1t);
    cudaGetSymbolAddress((void**)&w2t, g_w2t);

    constexpr int SMEM = 3 * (256 * 144 + 128 * 144);   // 165888
    cudaFuncSetAttribute(gemm_pipe_h<CONVC, EMBED, true,  true>,
                         cudaFuncAttributeMaxDynamicSharedMemorySize, SMEM);
    cudaFuncSetAttribute(gemm_pipe_h<HID, CONVC, true,  true>,
                         cudaFuncAttributeMaxDynamicSharedMemorySize, SMEM);
    cudaFuncSetAttribute(gemm_pipe_h<LABELS, HID, false, false>,
                         cudaFuncAttributeMaxDynamicSharedMemorySize, SMEM);

    // Prep: gather+cvt activations, cvt/transpose weights (bandwidth-trivial)
    gather_h_kernel<<<(M_TOTAL * EMBED / 4) / 256, 256>>>(tok, emb, x_buf);
    cvt_h_kernel<<<(CONVC * EMBED / 4) / 256, 256>>>(conv_w, w0);
    transpose_h_kernel<<<dim3(HID / 32, CONVC / 32), dim3(32, 8)>>>(w1, w1t, CONVC, HID);
    transpose_h_kernel<<<dim3(LABELS / 32, HID / 32), dim3(32, 8)>>>(w2, w2t, HID, LABELS);

    // GEMM1: h = fp16(relu(x @ conv_w^T + conv_b))    [32768, 512]
    gemm_pipe_h<CONVC, EMBED, true, true>
        <<<dim3(CONVC / 128, M_TOTAL / 256), 256, SMEM>>>(x_buf, w0, conv_b, h_buf);
    // GEMM2: z = fp16(relu(h @ w1 + b1))              [32768, 1024]
    gemm_pipe_h<HID, CONVC, true, true>
        <<<dim3(HID / 128, M_TOTAL / 256), 256, SMEM>>>(h_buf, w1t, b1, z_buf);
    // GEMM3: out = z @ w2 + b2                        [32768, 128]
    gemm_pipe_h<LABELS, HID, false, false>
        <<<dim3(LABELS / 128, M_TOTAL / 256), 256, SMEM>>>(z_buf, w2t, b2, out);
}